// round 6
// baseline (speedup 1.0000x reference)
#include <cuda_runtime.h>

#define NPTS   65536     // B*T
#define TPB    256
#define P      4
#define GPB    (TPB/8)   // 32 groups of 8 lanes
#define PPB    (GPB*P)   // 128 points per block
#define NBLKS  (NPTS/PPB)

typedef unsigned long long u64;

__device__ __forceinline__ u64 pk2(float a, float b) {
    u64 r; asm("mov.b64 %0, {%1,%2};" : "=l"(r) : "f"(a), "f"(b)); return r;
}
__device__ __forceinline__ u64 dup2(float a) { return pk2(a, a); }
__device__ __forceinline__ void upk2(u64 v, float& a, float& b) {
    asm("mov.b64 {%0,%1}, %2;" : "=f"(a), "=f"(b) : "l"(v));
}
__device__ __forceinline__ void fma2(u64& d, u64 a, u64 b) {
    asm("fma.rn.f32x2 %0, %1, %2, %0;" : "+l"(d) : "l"(a), "l"(b));
}
__device__ __forceinline__ u64 add2(u64 a, u64 b) {
    u64 r; asm("add.rn.f32x2 %0, %1, %2;" : "=l"(r) : "l"(a), "l"(b)); return r;
}

// dynamic smem float-offsets
#define OW0 0          // 5120
#define OW1 5120       // 5120
#define OB0 10240      // 160
#define OB1 10400      // 160
#define OWP 10560      // 96
#define OBP 10656      // 32
#define OWO 10688      // 32
#define OC  10720      // 32  (sC[4][8])
#define OBO 10752      // 1 (+15 pad)
#define OCF 10768      // cf region: 4 pp x 256 thr x 16B = 16KB
#define SMEM_BYTES ((10768 + 4096) * 4)   // 59456 B

__global__ __launch_bounds__(TPB, 3)
void decoder_fused_kernel(
    const float* __restrict__ p,      // [16,4096,3]
    const float* __restrict__ c,      // [16,4,128,128,32]
    const float* __restrict__ Cmat,   // [16,4,4,3]
    const float* __restrict__ fcpW,   // [3,32]
    const float* __restrict__ fcpb,   // [32]
    const float* __restrict__ W0,     // [5,32,32]
    const float* __restrict__ b0,     // [5,32]
    const float* __restrict__ W1,     // [5,32,32]
    const float* __restrict__ b1,     // [5,32]
    const float* __restrict__ Wout,   // [32,1]
    const float* __restrict__ bout,   // [1]
    float* __restrict__ out)          // [16,4096]
{
    extern __shared__ float sm[];
    ulonglong2* scf = (ulonglong2*)(sm + OCF);

    const int tid = threadIdx.x;
    const int q8  = tid & 7;                      // channel eighth: owns ch [q8*4, q8*4+4)
    const int g   = tid >> 3;                     // group id 0..31
    const int pt0 = blockIdx.x * PPB + g;
    const int b   = pt0 >> 12;                    // PPB divides 4096 -> block in one batch
    const int chb = q8 * 4;
    const unsigned FULL = 0xffffffffu;

    // ---- stage weights ----
    for (int i = tid; i < 5120; i += TPB) { sm[OW0 + i] = W0[i]; sm[OW1 + i] = W1[i]; }
    if (tid < 160) { sm[OB0 + tid] = b0[tid]; sm[OB1 + tid] = b1[tid]; }
    if (tid < 96) sm[OWP + tid] = fcpW[tid];
    if (tid < 32) { sm[OBP + tid] = fcpb[tid]; sm[OWO + tid] = Wout[tid]; }
    if (tid == 0) sm[OBO] = bout[0];
    if (tid < 28) {
        int l = tid / 7, k = tid % 7;
        const float* Cb = Cmat + (b * 4 + l) * 12;
        sm[OC + l * 8 + k] = (k < 6) ? Cb[k] : (Cb[9] + 0.05f);
    }
    __syncthreads();

    const float interval = 2.0f / 127.0f;

    float x[P][4];    // this lane's 4 channels for P points

    // ---- gather + fc_p per point; cf parked in smem ----
    #pragma unroll 1
    for (int pp = 0; pp < P; pp++) {
        const int pt = pt0 + pp * GPB;
        const float p0 = p[pt * 3 + 0];
        const float p1 = p[pt * 3 + 1];
        const float p2 = p[pt * 3 + 2];
        const float ps0 = p0 / 0.55f;
        const float ps1 = p1 / 0.55f;
        const float ps2 = p2 / 0.55f;

        u64 cf2[2];
        cf2[0] = 0ull; cf2[1] = 0ull;

        #pragma unroll
        for (int l = 0; l < 4; l++) {
            const float c00 = sm[OC + l*8 + 0], c01 = sm[OC + l*8 + 1], c02 = sm[OC + l*8 + 2];
            const float c10 = sm[OC + l*8 + 3], c11 = sm[OC + l*8 + 4], c12 = sm[OC + l*8 + 5];
            const float den = sm[OC + l*8 + 6];

            float px = (c00 * ps0 + c01 * ps1 + c02 * ps2) / den;
            float py = (c10 * ps0 + c11 * ps1 + c12 * ps2) / den;

            float xg = (px + 1.0f) / interval;
            float yg = (py + 1.0f) / interval;
            // match ref: first >=127 -> 126.9, then <0 -> 0
            xg = (xg >= 127.0f) ? 126.9f : xg;  xg = (xg < 0.0f) ? 0.0f : xg;
            yg = (yg >= 127.0f) ? 126.9f : yg;  yg = (yg < 0.0f) ? 0.0f : yg;

            // half-to-even rounding, same as jnp.round
            const float xl = rintf(xg - 0.5f), xr = rintf(xg + 0.5f);
            const float yl = rintf(yg - 0.5f), yh = rintf(yg + 0.5f);
            const int xil = (int)xl, xir = (int)xr;
            const int yil = (int)yl, yih = (int)yh;

            const float dx = xr - xg, dy = yh - yg;
            const u64 W11 = dup2(dx * dy);
            const u64 W12 = dup2((1.0f - dx) * dy);
            const u64 W21 = dup2(dx * (1.0f - dy));
            const u64 W22 = dup2((1.0f - dx) * (1.0f - dy));

            const int base = (b * 4 + l) * 128 * 128;
            // 8 lanes of a group cover one full 128B corner row (16B each)
            const ulonglong2 a  = *((const ulonglong2*)(c + (size_t)(base + xil * 128 + yil) * 32) + q8);
            const ulonglong2 e  = *((const ulonglong2*)(c + (size_t)(base + xir * 128 + yil) * 32) + q8);
            const ulonglong2 f  = *((const ulonglong2*)(c + (size_t)(base + xil * 128 + yih) * 32) + q8);
            const ulonglong2 gg = *((const ulonglong2*)(c + (size_t)(base + xir * 128 + yih) * 32) + q8);

            fma2(cf2[0], W11, a.x);   fma2(cf2[1], W11, a.y);
            fma2(cf2[0], W12, e.x);   fma2(cf2[1], W12, e.y);
            fma2(cf2[0], W21, f.x);   fma2(cf2[1], W21, f.y);
            fma2(cf2[0], W22, gg.x);  fma2(cf2[1], W22, gg.y);
        }

        // park cf in smem (own slot, no sync needed)
        scf[pp * TPB + tid] = make_ulonglong2(cf2[0], cf2[1]);

        // fc_p (cf added at top of block 0 below)
        #pragma unroll
        for (int j = 0; j < 4; j++) {
            const int ch = chb + j;
            float v = sm[OBP + ch];
            v = fmaf(p0, sm[OWP + ch],      v);
            v = fmaf(p1, sm[OWP + 32 + ch], v);
            v = fmaf(p2, sm[OWP + 64 + ch], v);
            x[pp][j] = v;
        }
    }

    // ---- 5 resnet blocks; cf re-added at top of each (incl. blk0 = ref's net+cf) ----
    #pragma unroll 1
    for (int blk = 0; blk < 5; blk++) {
        #pragma unroll
        for (int pp = 0; pp < P; pp++) {
            const ulonglong2 cv = scf[pp * TPB + tid];
            float c0, c1, c2, c3;
            upk2(cv.x, c0, c1); upk2(cv.y, c2, c3);
            x[pp][0] += c0; x[pp][1] += c1; x[pp][2] += c2; x[pp][3] += c3;
        }

        // ---- h = relu(x) @ W0 + b0 ----
        u64 acc[P][2];
        {
            const ulonglong2 bb = *(const ulonglong2*)(sm + OB0 + blk * 32 + chb);
            #pragma unroll
            for (int pp = 0; pp < P; pp++) { acc[pp][0] = bb.x; acc[pp][1] = bb.y; }
        }
        {
            const float* wbase = sm + OW0 + blk * 1024 + chb;
            #pragma unroll
            for (int k = 0; k < 32; k++) {
                const ulonglong2 w = *(const ulonglong2*)(wbase + k * 32);
                const int o = k >> 2, ii = k & 3;
                #pragma unroll
                for (int pp = 0; pp < P; pp++) {
                    const float v = fmaxf(__shfl_sync(FULL, x[pp][ii], o, 8), 0.0f);
                    const u64 vv = dup2(v);
                    fma2(acc[pp][0], vv, w.x);
                    fma2(acc[pp][1], vv, w.y);
                }
            }
        }

        // relu(h) in place (h dead after gemv1)
        float h[P][4];
        #pragma unroll
        for (int pp = 0; pp < P; pp++) {
            upk2(acc[pp][0], h[pp][0], h[pp][1]);
            upk2(acc[pp][1], h[pp][2], h[pp][3]);
            h[pp][0] = fmaxf(h[pp][0], 0.0f);
            h[pp][1] = fmaxf(h[pp][1], 0.0f);
            h[pp][2] = fmaxf(h[pp][2], 0.0f);
            h[pp][3] = fmaxf(h[pp][3], 0.0f);
        }

        // ---- x += b1; x += relu(h) @ W1 (packed accumulation into xp) ----
        u64 xp[P][2];
        {
            const ulonglong2 bb = *(const ulonglong2*)(sm + OB1 + blk * 32 + chb);
            #pragma unroll
            for (int pp = 0; pp < P; pp++) {
                xp[pp][0] = add2(pk2(x[pp][0], x[pp][1]), bb.x);
                xp[pp][1] = add2(pk2(x[pp][2], x[pp][3]), bb.y);
            }
        }
        {
            const float* wbase = sm + OW1 + blk * 1024 + chb;
            #pragma unroll
            for (int k = 0; k < 32; k++) {
                const ulonglong2 w = *(const ulonglong2*)(wbase + k * 32);
                const int o = k >> 2, ii = k & 3;
                #pragma unroll
                for (int pp = 0; pp < P; pp++) {
                    const u64 vv = dup2(__shfl_sync(FULL, h[pp][ii], o, 8));
                    fma2(xp[pp][0], vv, w.x);
                    fma2(xp[pp][1], vv, w.y);
                }
            }
        }
        #pragma unroll
        for (int pp = 0; pp < P; pp++) {
            upk2(xp[pp][0], x[pp][0], x[pp][1]);
            upk2(xp[pp][1], x[pp][2], x[pp][3]);
        }
    }

    // ---- output head: 4-channel partial dot, reduce over 8 lanes ----
    const float sbo = sm[OBO];
    #pragma unroll
    for (int pp = 0; pp < P; pp++) {
        float acc = 0.0f;
        #pragma unroll
        for (int j = 0; j < 4; j++)
            acc = fmaf(fmaxf(x[pp][j], 0.0f), sm[OWO + chb + j], acc);
        acc += __shfl_xor_sync(FULL, acc, 1);
        acc += __shfl_xor_sync(FULL, acc, 2);
        acc += __shfl_xor_sync(FULL, acc, 4);
        if (q8 == 0) out[pt0 + pp * GPB] = acc + sbo;
    }
}

extern "C" void kernel_launch(void* const* d_in, const int* in_sizes, int n_in,
                              void* d_out, int out_size)
{
    const float* p    = (const float*)d_in[0];
    // d_in[1] = z (unused by the reference graph)
    const float* c    = (const float*)d_in[2];
    const float* Cm   = (const float*)d_in[3];
    const float* fpW  = (const float*)d_in[4];
    const float* fpb  = (const float*)d_in[5];
    const float* W0   = (const float*)d_in[6];
    const float* b0   = (const float*)d_in[7];
    const float* W1   = (const float*)d_in[8];
    const float* b1   = (const float*)d_in[9];
    const float* Wo   = (const float*)d_in[10];
    const float* bo   = (const float*)d_in[11];
    float* out = (float*)d_out;

    cudaFuncSetAttribute(decoder_fused_kernel,
                         cudaFuncAttributeMaxDynamicSharedMemorySize, SMEM_BYTES);
    decoder_fused_kernel<<<NBLKS, TPB, SMEM_BYTES>>>(p, c, Cm, fpW, fpb, W0, b0, W1, b1, Wo, bo, out);
}

// round 7
// speedup vs baseline: 1.4127x; 1.4127x over previous
#include <cuda_runtime.h>

#define NPTS   65536     // B*T
#define TPB    256
#define P      4
#define GPB    64        // groups per block (4 lanes each)
#define PPB    256       // points per block
#define NBLKS  (NPTS/PPB)

typedef unsigned long long u64;

__device__ __forceinline__ u64 pk2(float a, float b) {
    u64 r; asm("mov.b64 %0, {%1,%2};" : "=l"(r) : "f"(a), "f"(b)); return r;
}
__device__ __forceinline__ u64 dup2(float a) { return pk2(a, a); }
__device__ __forceinline__ void upk2(u64 v, float& a, float& b) {
    asm("mov.b64 {%0,%1}, %2;" : "=f"(a), "=f"(b) : "l"(v));
}
__device__ __forceinline__ void fma2(u64& d, u64 a, u64 b) {
    asm("fma.rn.f32x2 %0, %1, %2, %0;" : "+l"(d) : "l"(a), "l"(b));
}
__device__ __forceinline__ u64 add2(u64 a, u64 b) {
    u64 r; asm("add.rn.f32x2 %0, %1, %2;" : "=l"(r) : "l"(a), "l"(b)); return r;
}

// dynamic smem float-offsets
#define OW0 0          // 5120
#define OW1 5120       // 5120
#define OB0 10240      // 160
#define OB1 10400      // 160
#define OWP 10560      // 96
#define OBP 10656      // 32
#define OWO 10688      // 32
#define OC  10720      // 32  (sC[4][8])
#define OBO 10752      // 1 (+15 pad)
#define OCF 10768      // cf region: 4 pp x 256 thr x 16B = 32KB
#define OXB 18960      // activation broadcast: P x 64 groups x 36 floats = 9216 fl
#define XSTR 36        // padded stride (bank-conflict-free group broadcast)
#define SMEM_BYTES ((18960 + 9216) * 4)   // 112704 B

__global__ __launch_bounds__(TPB, 2)
void decoder_fused_kernel(
    const float* __restrict__ p,      // [16,4096,3]
    const float* __restrict__ c,      // [16,4,128,128,32]
    const float* __restrict__ Cmat,   // [16,4,4,3]
    const float* __restrict__ fcpW,   // [3,32]
    const float* __restrict__ fcpb,   // [32]
    const float* __restrict__ W0,     // [5,32,32]
    const float* __restrict__ b0,     // [5,32]
    const float* __restrict__ W1,     // [5,32,32]
    const float* __restrict__ b1,     // [5,32]
    const float* __restrict__ Wout,   // [32,1]
    const float* __restrict__ bout,   // [1]
    float* __restrict__ out)          // [16,4096]
{
    extern __shared__ float sm[];
    ulonglong2* scf = (ulonglong2*)(sm + OCF);

    const int tid = threadIdx.x;
    const int q4  = tid & 3;                      // channel quarter: ch [q4*8, q4*8+8)
    const int g   = tid >> 2;                     // group id 0..63
    const int pt0 = blockIdx.x * PPB + g;
    const int b   = pt0 >> 12;                    // block stays in one batch
    const int chb = q4 * 8;
    const unsigned FULL = 0xffffffffu;

    // ---- stage weights ----
    for (int i = tid; i < 5120; i += TPB) { sm[OW0 + i] = W0[i]; sm[OW1 + i] = W1[i]; }
    if (tid < 160) { sm[OB0 + tid] = b0[tid]; sm[OB1 + tid] = b1[tid]; }
    if (tid < 96) sm[OWP + tid] = fcpW[tid];
    if (tid < 32) { sm[OBP + tid] = fcpb[tid]; sm[OWO + tid] = Wout[tid]; }
    if (tid == 0) sm[OBO] = bout[0];
    if (tid < 28) {
        int l = tid / 7, k = tid % 7;
        const float* Cb = Cmat + (b * 4 + l) * 12;
        sm[OC + l * 8 + k] = (k < 6) ? Cb[k] : (Cb[9] + 0.05f);
    }
    __syncthreads();

    const float interval = 2.0f / 127.0f;

    float x[P][8];    // this lane's 8 channels for P points (pre-activation)

    // ---- gather + fc_p per point; cf parked in smem ----
    #pragma unroll 1
    for (int pp = 0; pp < P; pp++) {
        const int pt = pt0 + pp * GPB;
        const float p0 = p[pt * 3 + 0];
        const float p1 = p[pt * 3 + 1];
        const float p2 = p[pt * 3 + 2];
        const float ps0 = p0 / 0.55f;
        const float ps1 = p1 / 0.55f;
        const float ps2 = p2 / 0.55f;

        u64 cf2[4];
        #pragma unroll
        for (int m = 0; m < 4; m++) cf2[m] = 0ull;

        #pragma unroll
        for (int l = 0; l < 4; l++) {
            const float c00 = sm[OC + l*8 + 0], c01 = sm[OC + l*8 + 1], c02 = sm[OC + l*8 + 2];
            const float c10 = sm[OC + l*8 + 3], c11 = sm[OC + l*8 + 4], c12 = sm[OC + l*8 + 5];
            const float den = sm[OC + l*8 + 6];

            float px = (c00 * ps0 + c01 * ps1 + c02 * ps2) / den;
            float py = (c10 * ps0 + c11 * ps1 + c12 * ps2) / den;

            float xg = (px + 1.0f) / interval;
            float yg = (py + 1.0f) / interval;
            xg = (xg >= 127.0f) ? 126.9f : xg;  xg = (xg < 0.0f) ? 0.0f : xg;
            yg = (yg >= 127.0f) ? 126.9f : yg;  yg = (yg < 0.0f) ? 0.0f : yg;

            const float xl = rintf(xg - 0.5f), xr = rintf(xg + 0.5f);
            const float yl = rintf(yg - 0.5f), yh = rintf(yg + 0.5f);
            const int xil = (int)xl, xir = (int)xr;
            const int yil = (int)yl, yih = (int)yh;

            const float dx = xr - xg, dy = yh - yg;
            const u64 W11 = dup2(dx * dy);
            const u64 W12 = dup2((1.0f - dx) * dy);
            const u64 W21 = dup2(dx * (1.0f - dy));
            const u64 W22 = dup2((1.0f - dx) * (1.0f - dy));

            const int base = (b * 4 + l) * 128 * 128;
            const ulonglong2* r11 = (const ulonglong2*)(c + (size_t)(base + xil * 128 + yil) * 32) + q4 * 2;
            const ulonglong2* r12 = (const ulonglong2*)(c + (size_t)(base + xir * 128 + yil) * 32) + q4 * 2;
            const ulonglong2* r21 = (const ulonglong2*)(c + (size_t)(base + xil * 128 + yih) * 32) + q4 * 2;
            const ulonglong2* r22 = (const ulonglong2*)(c + (size_t)(base + xir * 128 + yih) * 32) + q4 * 2;

            #pragma unroll
            for (int q = 0; q < 2; q++) {
                const ulonglong2 a  = r11[q];
                const ulonglong2 e  = r12[q];
                const ulonglong2 f  = r21[q];
                const ulonglong2 gg = r22[q];
                fma2(cf2[2*q    ], W11, a.x);   fma2(cf2[2*q + 1], W11, a.y);
                fma2(cf2[2*q    ], W12, e.x);   fma2(cf2[2*q + 1], W12, e.y);
                fma2(cf2[2*q    ], W21, f.x);   fma2(cf2[2*q + 1], W21, f.y);
                fma2(cf2[2*q    ], W22, gg.x);  fma2(cf2[2*q + 1], W22, gg.y);
            }
        }

        scf[(pp * 2 + 0) * TPB + tid] = make_ulonglong2(cf2[0], cf2[1]);
        scf[(pp * 2 + 1) * TPB + tid] = make_ulonglong2(cf2[2], cf2[3]);

        #pragma unroll
        for (int j = 0; j < 8; j++) {
            const int ch = chb + j;
            float v = sm[OBP + ch];
            v = fmaf(p0, sm[OWP + ch],      v);
            v = fmaf(p1, sm[OWP + 32 + ch], v);
            v = fmaf(p2, sm[OWP + 64 + ch], v);
            x[pp][j] = v;
        }
    }

    float* const xb = sm + OXB;

    // ---- 5 resnet blocks; cf re-added at top of each ----
    #pragma unroll 1
    for (int blk = 0; blk < 5; blk++) {
        __syncwarp(FULL);   // prev GEMV1 reads done before overwriting buffer

        // cf add + park relu(x) for broadcast
        #pragma unroll
        for (int pp = 0; pp < P; pp++) {
            const ulonglong2 ca = scf[(pp * 2 + 0) * TPB + tid];
            const ulonglong2 cb = scf[(pp * 2 + 1) * TPB + tid];
            float c0, c1, c2, c3;
            upk2(ca.x, c0, c1); upk2(ca.y, c2, c3);
            x[pp][0] += c0; x[pp][1] += c1; x[pp][2] += c2; x[pp][3] += c3;
            upk2(cb.x, c0, c1); upk2(cb.y, c2, c3);
            x[pp][4] += c0; x[pp][5] += c1; x[pp][6] += c2; x[pp][7] += c3;

            float* dst = xb + (pp * GPB + g) * XSTR + chb;
            *(float4*)(dst)     = make_float4(fmaxf(x[pp][0],0.f), fmaxf(x[pp][1],0.f),
                                              fmaxf(x[pp][2],0.f), fmaxf(x[pp][3],0.f));
            *(float4*)(dst + 4) = make_float4(fmaxf(x[pp][4],0.f), fmaxf(x[pp][5],0.f),
                                              fmaxf(x[pp][6],0.f), fmaxf(x[pp][7],0.f));
        }
        __syncwarp(FULL);

        // ---- h = relu(x) @ W0 + b0 ----
        u64 acc[P][4];
        {
            const ulonglong2* bb = (const ulonglong2*)(sm + OB0 + blk * 32 + chb);
            const ulonglong2 b01 = bb[0], b23 = bb[1];
            #pragma unroll
            for (int pp = 0; pp < P; pp++) {
                acc[pp][0] = b01.x; acc[pp][1] = b01.y;
                acc[pp][2] = b23.x; acc[pp][3] = b23.y;
            }
        }
        {
            const float* wbase = sm + OW0 + blk * 1024 + chb;
            #pragma unroll
            for (int kc = 0; kc < 8; kc++) {
                ulonglong2 w[4][2];
                #pragma unroll
                for (int i = 0; i < 4; i++) {
                    const ulonglong2* r = (const ulonglong2*)(wbase + (kc*4 + i) * 32);
                    w[i][0] = r[0]; w[i][1] = r[1];
                }
                #pragma unroll
                for (int pp = 0; pp < P; pp++) {
                    const float4 xv = *(const float4*)(xb + (pp * GPB + g) * XSTR + kc * 4);
                    u64 vv;
                    vv = dup2(xv.x);
                    fma2(acc[pp][0], vv, w[0][0].x); fma2(acc[pp][1], vv, w[0][0].y);
                    fma2(acc[pp][2], vv, w[0][1].x); fma2(acc[pp][3], vv, w[0][1].y);
                    vv = dup2(xv.y);
                    fma2(acc[pp][0], vv, w[1][0].x); fma2(acc[pp][1], vv, w[1][0].y);
                    fma2(acc[pp][2], vv, w[1][1].x); fma2(acc[pp][3], vv, w[1][1].y);
                    vv = dup2(xv.z);
                    fma2(acc[pp][0], vv, w[2][0].x); fma2(acc[pp][1], vv, w[2][0].y);
                    fma2(acc[pp][2], vv, w[2][1].x); fma2(acc[pp][3], vv, w[2][1].y);
                    vv = dup2(xv.w);
                    fma2(acc[pp][0], vv, w[3][0].x); fma2(acc[pp][1], vv, w[3][0].y);
                    fma2(acc[pp][2], vv, w[3][1].x); fma2(acc[pp][3], vv, w[3][1].y);
                }
            }
        }
        __syncwarp(FULL);   // GEMV0 reads done before overwriting buffer with relu(h)

        // park relu(h)
        #pragma unroll
        for (int pp = 0; pp < P; pp++) {
            float h0,h1,h2,h3,h4,h5,h6,h7;
            upk2(acc[pp][0], h0, h1); upk2(acc[pp][1], h2, h3);
            upk2(acc[pp][2], h4, h5); upk2(acc[pp][3], h6, h7);
            float* dst = xb + (pp * GPB + g) * XSTR + chb;
            *(float4*)(dst)     = make_float4(fmaxf(h0,0.f), fmaxf(h1,0.f),
                                              fmaxf(h2,0.f), fmaxf(h3,0.f));
            *(float4*)(dst + 4) = make_float4(fmaxf(h4,0.f), fmaxf(h5,0.f),
                                              fmaxf(h6,0.f), fmaxf(h7,0.f));
        }
        __syncwarp(FULL);

        // ---- x += b1; x += relu(h) @ W1 ----
        u64 xp[P][4];
        {
            const ulonglong2* bb = (const ulonglong2*)(sm + OB1 + blk * 32 + chb);
            const ulonglong2 b01 = bb[0], b23 = bb[1];
            #pragma unroll
            for (int pp = 0; pp < P; pp++) {
                xp[pp][0] = add2(pk2(x[pp][0], x[pp][1]), b01.x);
                xp[pp][1] = add2(pk2(x[pp][2], x[pp][3]), b01.y);
                xp[pp][2] = add2(pk2(x[pp][4], x[pp][5]), b23.x);
                xp[pp][3] = add2(pk2(x[pp][6], x[pp][7]), b23.y);
            }
        }
        {
            const float* wbase = sm + OW1 + blk * 1024 + chb;
            #pragma unroll
            for (int kc = 0; kc < 8; kc++) {
                ulonglong2 w[4][2];
                #pragma unroll
                for (int i = 0; i < 4; i++) {
                    const ulonglong2* r = (const ulonglong2*)(wbase + (kc*4 + i) * 32);
                    w[i][0] = r[0]; w[i][1] = r[1];
                }
                #pragma unroll
                for (int pp = 0; pp < P; pp++) {
                    const float4 xv = *(const float4*)(xb + (pp * GPB + g) * XSTR + kc * 4);
                    u64 vv;
                    vv = dup2(xv.x);
                    fma2(xp[pp][0], vv, w[0][0].x); fma2(xp[pp][1], vv, w[0][0].y);
                    fma2(xp[pp][2], vv, w[0][1].x); fma2(xp[pp][3], vv, w[0][1].y);
                    vv = dup2(xv.y);
                    fma2(xp[pp][0], vv, w[1][0].x); fma2(xp[pp][1], vv, w[1][0].y);
                    fma2(xp[pp][2], vv, w[1][1].x); fma2(xp[pp][3], vv, w[1][1].y);
                    vv = dup2(xv.z);
                    fma2(xp[pp][0], vv, w[2][0].x); fma2(xp[pp][1], vv, w[2][0].y);
                    fma2(xp[pp][2], vv, w[2][1].x); fma2(xp[pp][3], vv, w[2][1].y);
                    vv = dup2(xv.w);
                    fma2(xp[pp][0], vv, w[3][0].x); fma2(xp[pp][1], vv, w[3][0].y);
                    fma2(xp[pp][2], vv, w[3][1].x); fma2(xp[pp][3], vv, w[3][1].y);
                }
            }
        }
        #pragma unroll
        for (int pp = 0; pp < P; pp++) {
            upk2(xp[pp][0], x[pp][0], x[pp][1]);
            upk2(xp[pp][1], x[pp][2], x[pp][3]);
            upk2(xp[pp][2], x[pp][4], x[pp][5]);
            upk2(xp[pp][3], x[pp][6], x[pp][7]);
        }
    }

    // ---- output head ----
    const float sbo = sm[OBO];
    #pragma unroll
    for (int pp = 0; pp < P; pp++) {
        float acc = 0.0f;
        #pragma unroll
        for (int j = 0; j < 8; j++)
            acc = fmaf(fmaxf(x[pp][j], 0.0f), sm[OWO + chb + j], acc);
        acc += __shfl_xor_sync(FULL, acc, 1);
        acc += __shfl_xor_sync(FULL, acc, 2);
        if (q4 == 0) out[pt0 + pp * GPB] = acc + sbo;
    }
}

extern "C" void kernel_launch(void* const* d_in, const int* in_sizes, int n_in,
                              void* d_out, int out_size)
{
    const float* p    = (const float*)d_in[0];
    // d_in[1] = z (unused by the reference graph)
    const float* c    = (const float*)d_in[2];
    const float* Cm   = (const float*)d_in[3];
    const float* fpW  = (const float*)d_in[4];
    const float* fpb  = (const float*)d_in[5];
    const float* W0   = (const float*)d_in[6];
    const float* b0   = (const float*)d_in[7];
    const float* W1   = (const float*)d_in[8];
    const float* b1   = (const float*)d_in[9];
    const float* Wo   = (const float*)d_in[10];
    const float* bo   = (const float*)d_in[11];
    float* out = (float*)d_out;

    cudaFuncSetAttribute(decoder_fused_kernel,
                         cudaFuncAttributeMaxDynamicSharedMemorySize, SMEM_BYTES);
    decoder_fused_kernel<<<NBLKS, TPB, SMEM_BYTES>>>(p, c, Cm, fpW, fpb, W0, b0, W1, b1, Wo, bo, out);
}

// round 8
// speedup vs baseline: 1.5677x; 1.1097x over previous
#include <cuda_runtime.h>

#define NPTS   65536     // B*T
#define TPB    256
#define P      4
#define GPB    64        // groups per block (4 lanes each)
#define PPB    256       // points per block
#define NBLKS  (NPTS/PPB)

typedef unsigned long long u64;

__device__ __forceinline__ u64 pk2(float a, float b) {
    u64 r; asm("mov.b64 %0, {%1,%2};" : "=l"(r) : "f"(a), "f"(b)); return r;
}
__device__ __forceinline__ u64 dup2(float a) { return pk2(a, a); }
__device__ __forceinline__ void upk2(u64 v, float& a, float& b) {
    asm("mov.b64 {%0,%1}, %2;" : "=f"(a), "=f"(b) : "l"(v));
}
__device__ __forceinline__ void fma2(u64& d, u64 a, u64 b) {
    asm("fma.rn.f32x2 %0, %1, %2, %0;" : "+l"(d) : "l"(a), "l"(b));
}
__device__ __forceinline__ u64 add2(u64 a, u64 b) {
    u64 r; asm("add.rn.f32x2 %0, %1, %2;" : "=l"(r) : "l"(a), "l"(b)); return r;
}

// dynamic smem float-offsets
#define OW0 0          // 5120
#define OW1 5120       // 5120
#define OB0 10240      // 160
#define OB1 10400      // 160
#define OWP 10560      // 96
#define OBP 10656      // 32
#define OWO 10688      // 32
#define OC  10720      // 32  (sC[4][8]; [6] = 1/den)
#define OBO 10752      // 1 (+15 pad)
#define OCF 10768      // cf region: 4 pp x 256 thr x 16B = 32KB
#define OXB 18960      // activation broadcast: P x 64 groups x 36 floats
#define XSTR 36        // padded stride (bank-conflict-free group broadcast)
#define SMEM_BYTES ((18960 + 9216) * 4)   // 112704 B

__global__ __launch_bounds__(TPB, 2)
void decoder_fused_kernel(
    const float* __restrict__ p,      // [16,4096,3]
    const float* __restrict__ c,      // [16,4,128,128,32]
    const float* __restrict__ Cmat,   // [16,4,4,3]
    const float* __restrict__ fcpW,   // [3,32]
    const float* __restrict__ fcpb,   // [32]
    const float* __restrict__ W0,     // [5,32,32]
    const float* __restrict__ b0,     // [5,32]
    const float* __restrict__ W1,     // [5,32,32]
    const float* __restrict__ b1,     // [5,32]
    const float* __restrict__ Wout,   // [32,1]
    const float* __restrict__ bout,   // [1]
    float* __restrict__ out)          // [16,4096]
{
    extern __shared__ float sm[];
    ulonglong2* scf = (ulonglong2*)(sm + OCF);

    const int tid = threadIdx.x;
    const int q4  = tid & 3;                      // channel quarter: ch [q4*8, q4*8+8)
    const int g   = tid >> 2;                     // group id 0..63
    const int pt0 = blockIdx.x * PPB + g;
    const int b   = pt0 >> 12;                    // block stays in one batch
    const int chb = q4 * 8;
    const unsigned FULL = 0xffffffffu;

    // ---- stage weights ----
    for (int i = tid; i < 5120; i += TPB) { sm[OW0 + i] = W0[i]; sm[OW1 + i] = W1[i]; }
    if (tid < 160) { sm[OB0 + tid] = b0[tid]; sm[OB1 + tid] = b1[tid]; }
    if (tid < 96) sm[OWP + tid] = fcpW[tid];
    if (tid < 32) { sm[OBP + tid] = fcpb[tid]; sm[OWO + tid] = Wout[tid]; }
    if (tid == 0) sm[OBO] = bout[0];
    if (tid < 28) {
        int l = tid / 7, k = tid % 7;
        const float* Cb = Cmat + (b * 4 + l) * 12;
        // k==6: store reciprocal of denominator (exact IEEE divide, once per (b,l))
        sm[OC + l * 8 + k] = (k < 6) ? Cb[k] : (1.0f / (Cb[9] + 0.05f));
    }
    __syncthreads();

    float x[P][8];    // this lane's 8 channels for P points (pre-activation)

    // ---- bilinear gather + fc_p, all P points unrolled (overlapped LDG latency) ----
    #pragma unroll
    for (int pp = 0; pp < P; pp++) {
        const int pt = pt0 + pp * GPB;
        const float p0 = p[pt * 3 + 0];
        const float p1 = p[pt * 3 + 1];
        const float p2 = p[pt * 3 + 2];
        const float ps0 = p0 / 0.55f;
        const float ps1 = p1 / 0.55f;
        const float ps2 = p2 / 0.55f;

        u64 cf2[4];
        #pragma unroll
        for (int m = 0; m < 4; m++) cf2[m] = 0ull;

        #pragma unroll
        for (int l = 0; l < 4; l++) {
            const float c00 = sm[OC + l*8 + 0], c01 = sm[OC + l*8 + 1], c02 = sm[OC + l*8 + 2];
            const float c10 = sm[OC + l*8 + 3], c11 = sm[OC + l*8 + 4], c12 = sm[OC + l*8 + 5];
            const float rden = sm[OC + l*8 + 6];

            const float px = (c00 * ps0 + c01 * ps1 + c02 * ps2) * rden;
            const float py = (c10 * ps0 + c11 * ps1 + c12 * ps2) * rden;

            float xg = fmaf(px, 63.5f, 63.5f);   // (px + 1) / (2/127)
            float yg = fmaf(py, 63.5f, 63.5f);
            xg = (xg >= 127.0f) ? 126.9f : xg;  xg = (xg < 0.0f) ? 0.0f : xg;
            yg = (yg >= 127.0f) ? 126.9f : yg;  yg = (yg < 0.0f) ? 0.0f : yg;

            // half-to-even rounding, same as jnp.round
            const float xl = rintf(xg - 0.5f), xr = rintf(xg + 0.5f);
            const float yl = rintf(yg - 0.5f), yh = rintf(yg + 0.5f);
            const int xil = (int)xl, xir = (int)xr;
            const int yil = (int)yl, yih = (int)yh;

            const float dx = xr - xg, dy = yh - yg;
            const u64 W11 = dup2(dx * dy);
            const u64 W12 = dup2((1.0f - dx) * dy);
            const u64 W21 = dup2(dx * (1.0f - dy));
            const u64 W22 = dup2((1.0f - dx) * (1.0f - dy));

            const int base = (b * 4 + l) * 128 * 128;
            const ulonglong2* r11 = (const ulonglong2*)(c + (size_t)(base + xil * 128 + yil) * 32) + q4 * 2;
            const ulonglong2* r12 = (const ulonglong2*)(c + (size_t)(base + xir * 128 + yil) * 32) + q4 * 2;
            const ulonglong2* r21 = (const ulonglong2*)(c + (size_t)(base + xil * 128 + yih) * 32) + q4 * 2;
            const ulonglong2* r22 = (const ulonglong2*)(c + (size_t)(base + xir * 128 + yih) * 32) + q4 * 2;

            #pragma unroll
            for (int q = 0; q < 2; q++) {
                const ulonglong2 a  = r11[q];
                const ulonglong2 e  = r12[q];
                const ulonglong2 f  = r21[q];
                const ulonglong2 gg = r22[q];
                fma2(cf2[2*q    ], W11, a.x);   fma2(cf2[2*q + 1], W11, a.y);
                fma2(cf2[2*q    ], W12, e.x);   fma2(cf2[2*q + 1], W12, e.y);
                fma2(cf2[2*q    ], W21, f.x);   fma2(cf2[2*q + 1], W21, f.y);
                fma2(cf2[2*q    ], W22, gg.x);  fma2(cf2[2*q + 1], W22, gg.y);
            }
        }

        scf[(pp * 2 + 0) * TPB + tid] = make_ulonglong2(cf2[0], cf2[1]);
        scf[(pp * 2 + 1) * TPB + tid] = make_ulonglong2(cf2[2], cf2[3]);

        #pragma unroll
        for (int j = 0; j < 8; j++) {
            const int ch = chb + j;
            float v = sm[OBP + ch];
            v = fmaf(p0, sm[OWP + ch],      v);
            v = fmaf(p1, sm[OWP + 32 + ch], v);
            v = fmaf(p2, sm[OWP + 64 + ch], v);
            x[pp][j] = v;
        }
    }

    float* const xb = sm + OXB;

    // ---- 5 resnet blocks; cf re-added at top of each ----
    #pragma unroll 1
    for (int blk = 0; blk < 5; blk++) {
        __syncwarp(FULL);   // prev GEMV1 reads done before overwriting buffer

        // cf add + park relu(x) for broadcast
        #pragma unroll
        for (int pp = 0; pp < P; pp++) {
            const ulonglong2 ca = scf[(pp * 2 + 0) * TPB + tid];
            const ulonglong2 cb = scf[(pp * 2 + 1) * TPB + tid];
            float c0, c1, c2, c3;
            upk2(ca.x, c0, c1); upk2(ca.y, c2, c3);
            x[pp][0] += c0; x[pp][1] += c1; x[pp][2] += c2; x[pp][3] += c3;
            upk2(cb.x, c0, c1); upk2(cb.y, c2, c3);
            x[pp][4] += c0; x[pp][5] += c1; x[pp][6] += c2; x[pp][7] += c3;

            float* dst = xb + (pp * GPB + g) * XSTR + chb;
            *(float4*)(dst)     = make_float4(fmaxf(x[pp][0],0.f), fmaxf(x[pp][1],0.f),
                                              fmaxf(x[pp][2],0.f), fmaxf(x[pp][3],0.f));
            *(float4*)(dst + 4) = make_float4(fmaxf(x[pp][4],0.f), fmaxf(x[pp][5],0.f),
                                              fmaxf(x[pp][6],0.f), fmaxf(x[pp][7],0.f));
        }
        __syncwarp(FULL);

        // ---- h = relu(x) @ W0 + b0 ----
        u64 acc[P][4];
        {
            const ulonglong2* bb = (const ulonglong2*)(sm + OB0 + blk * 32 + chb);
            const ulonglong2 b01 = bb[0], b23 = bb[1];
            #pragma unroll
            for (int pp = 0; pp < P; pp++) {
                acc[pp][0] = b01.x; acc[pp][1] = b01.y;
                acc[pp][2] = b23.x; acc[pp][3] = b23.y;
            }
        }
        {
            const float* wbase = sm + OW0 + blk * 1024 + chb;
            #pragma unroll
            for (int kc = 0; kc < 8; kc++) {
                ulonglong2 w[4][2];
                #pragma unroll
                for (int i = 0; i < 4; i++) {
                    const ulonglong2* r = (const ulonglong2*)(wbase + (kc*4 + i) * 32);
                    w[i][0] = r[0]; w[i][1] = r[1];
                }
                #pragma unroll
                for (int pp = 0; pp < P; pp++) {
                    const float4 xv = *(const float4*)(xb + (pp * GPB + g) * XSTR + kc * 4);
                    u64 vv;
                    vv = dup2(xv.x);
                    fma2(acc[pp][0], vv, w[0][0].x); fma2(acc[pp][1], vv, w[0][0].y);
                    fma2(acc[pp][2], vv, w[0][1].x); fma2(acc[pp][3], vv, w[0][1].y);
                    vv = dup2(xv.y);
                    fma2(acc[pp][0], vv, w[1][0].x); fma2(acc[pp][1], vv, w[1][0].y);
                    fma2(acc[pp][2], vv, w[1][1].x); fma2(acc[pp][3], vv, w[1][1].y);
                    vv = dup2(xv.z);
                    fma2(acc[pp][0], vv, w[2][0].x); fma2(acc[pp][1], vv, w[2][0].y);
                    fma2(acc[pp][2], vv, w[2][1].x); fma2(acc[pp][3], vv, w[2][1].y);
                    vv = dup2(xv.w);
                    fma2(acc[pp][0], vv, w[3][0].x); fma2(acc[pp][1], vv, w[3][0].y);
                    fma2(acc[pp][2], vv, w[3][1].x); fma2(acc[pp][3], vv, w[3][1].y);
                }
            }
        }
        __syncwarp(FULL);   // GEMV0 reads done before overwriting buffer with relu(h)

        // park relu(h)
        #pragma unroll
        for (int pp = 0; pp < P; pp++) {
            float h0,h1,h2,h3,h4,h5,h6,h7;
            upk2(acc[pp][0], h0, h1); upk2(acc[pp][1], h2, h3);
            upk2(acc[pp][2], h4, h5); upk2(acc[pp][3], h6, h7);
            float* dst = xb + (pp * GPB + g) * XSTR + chb;
            *(float4*)(dst)     = make_float4(fmaxf(h0,0.f), fmaxf(h1,0.f),
                                              fmaxf(h2,0.f), fmaxf(h3,0.f));
            *(float4*)(dst + 4) = make_float4(fmaxf(h4,0.f), fmaxf(h5,0.f),
                                              fmaxf(h6,0.f), fmaxf(h7,0.f));
        }
        __syncwarp(FULL);

        // ---- x += b1; x += relu(h) @ W1 ----
        u64 xp[P][4];
        {
            const ulonglong2* bb = (const ulonglong2*)(sm + OB1 + blk * 32 + chb);
            const ulonglong2 b01 = bb[0], b23 = bb[1];
            #pragma unroll
            for (int pp = 0; pp < P; pp++) {
                xp[pp][0] = add2(pk2(x[pp][0], x[pp][1]), b01.x);
                xp[pp][1] = add2(pk2(x[pp][2], x[pp][3]), b01.y);
                xp[pp][2] = add2(pk2(x[pp][4], x[pp][5]), b23.x);
                xp[pp][3] = add2(pk2(x[pp][6], x[pp][7]), b23.y);
            }
        }
        {
            const float* wbase = sm + OW1 + blk * 1024 + chb;
            #pragma unroll
            for (int kc = 0; kc < 8; kc++) {
                ulonglong2 w[4][2];
                #pragma unroll
                for (int i = 0; i < 4; i++) {
                    const ulonglong2* r = (const ulonglong2*)(wbase + (kc*4 + i) * 32);
                    w[i][0] = r[0]; w[i][1] = r[1];
                }
                #pragma unroll
                for (int pp = 0; pp < P; pp++) {
                    const float4 xv = *(const float4*)(xb + (pp * GPB + g) * XSTR + kc * 4);
                    u64 vv;
                    vv = dup2(xv.x);
                    fma2(xp[pp][0], vv, w[0][0].x); fma2(xp[pp][1], vv, w[0][0].y);
                    fma2(xp[pp][2], vv, w[0][1].x); fma2(xp[pp][3], vv, w[0][1].y);
                    vv = dup2(xv.y);
                    fma2(xp[pp][0], vv, w[1][0].x); fma2(xp[pp][1], vv, w[1][0].y);
                    fma2(xp[pp][2], vv, w[1][1].x); fma2(xp[pp][3], vv, w[1][1].y);
                    vv = dup2(xv.z);
                    fma2(xp[pp][0], vv, w[2][0].x); fma2(xp[pp][1], vv, w[2][0].y);
                    fma2(xp[pp][2], vv, w[2][1].x); fma2(xp[pp][3], vv, w[2][1].y);
                    vv = dup2(xv.w);
                    fma2(xp[pp][0], vv, w[3][0].x); fma2(xp[pp][1], vv, w[3][0].y);
                    fma2(xp[pp][2], vv, w[3][1].x); fma2(xp[pp][3], vv, w[3][1].y);
                }
            }
        }
        #pragma unroll
        for (int pp = 0; pp < P; pp++) {
            upk2(xp[pp][0], x[pp][0], x[pp][1]);
            upk2(xp[pp][1], x[pp][2], x[pp][3]);
            upk2(xp[pp][2], x[pp][4], x[pp][5]);
            upk2(xp[pp][3], x[pp][6], x[pp][7]);
        }
    }

    // ---- output head ----
    const float sbo = sm[OBO];
    #pragma unroll
    for (int pp = 0; pp < P; pp++) {
        float acc = 0.0f;
        #pragma unroll
        for (int j = 0; j < 8; j++)
            acc = fmaf(fmaxf(x[pp][j], 0.0f), sm[OWO + chb + j], acc);
        acc += __shfl_xor_sync(FULL, acc, 1);
        acc += __shfl_xor_sync(FULL, acc, 2);
        if (q4 == 0) out[pt0 + pp * GPB] = acc + sbo;
    }
}

extern "C" void kernel_launch(void* const* d_in, const int* in_sizes, int n_in,
                              void* d_out, int out_size)
{
    const float* p    = (const float*)d_in[0];
    // d_in[1] = z (unused by the reference graph)
    const float* c    = (const float*)d_in[2];
    const float* Cm   = (const float*)d_in[3];
    const float* fpW  = (const float*)d_in[4];
    const float* fpb  = (const float*)d_in[5];
    const float* W0   = (const float*)d_in[6];
    const float* b0   = (const float*)d_in[7];
    const float* W1   = (const float*)d_in[8];
    const float* b1   = (const float*)d_in[9];
    const float* Wo   = (const float*)d_in[10];
    const float* bo   = (const float*)d_in[11];
    float* out = (float*)d_out;

    cudaFuncSetAttribute(decoder_fused_kernel,
                         cudaFuncAttributeMaxDynamicSharedMemorySize, SMEM_BYTES);
    decoder_fused_kernel<<<NBLKS, TPB, SMEM_BYTES>>>(p, c, Cm, fpW, fpb, W0, b0, W1, b1, Wo, bo, out);
}